// round 16
// baseline (speedup 1.0000x reference)
#include <cuda_runtime.h>
#include <cstdint>

#define NQ   512
#define SS   2048
#define DD   128
#define TOPK 32
#define CLS  1000

#define CHUNK 256   // queries per attention launch

__device__ float g_summary[NQ * DD];

__device__ __forceinline__ float warp_sum(float v) {
    #pragma unroll
    for (int o = 16; o > 0; o >>= 1) v += __shfl_xor_sync(0xffffffffu, v, o);
    return v;
}

__device__ __forceinline__ void cp_async16(void* smem, const void* gmem) {
    uint32_t s = (uint32_t)__cvta_generic_to_shared(smem);
    asm volatile("cp.async.cg.shared.global [%0], [%1], 16;" :: "r"(s), "l"(gmem));
}

// monotone map: float total order == uint32 order. no NaNs in this data.
__device__ __forceinline__ uint32_t fmono(float x) {
    uint32_t b = __float_as_uint(x);
    return (b & 0x80000000u) ? ~b : (b | 0x80000000u);
}

// ---------------------------------------------------------------------------
// Fused attention (validated R8-R14), now chunked: n = n0 + blockIdx.x.
// ---------------------------------------------------------------------------
__global__ __launch_bounds__(256) void attn_topk_kernel(
    const float* __restrict__ q,
    const float* __restrict__ Kmat,
    const float* __restrict__ Vmat,
    float* __restrict__ weights_out,
    int n0)
{
    const int n    = n0 + blockIdx.x;
    const int tid  = threadIdx.x;
    const int warp = tid >> 5;
    const int lane = tid & 31;
    const int row4 = lane >> 3;
    const int g    = lane & 7;

    __shared__ __align__(16) float kring[8][2][4 * DD];  // 32 KB
    __shared__ float logits[SS];                         // 8 KB
    __shared__ uint32_t hist[4][256];                    // 4 KB
    __shared__ uint32_t sge[256];                        // 1 KB
    __shared__ uint32_t wsum[8];
    __shared__ int   s_topi[TOPK];
    __shared__ float s_w[TOPK];
    __shared__ int   eqbuf[64];
    __shared__ uint32_t s_prefix;
    __shared__ int   s_need, cA, cE;

    const float scale = 0.08838834764831845f; // 1/sqrt(128)

    float4 qf[4];
    {
        const float* qrow = q + (size_t)n * DD;
        #pragma unroll
        for (int j = 0; j < 4; j++)
            qf[j] = *reinterpret_cast<const float4*>(qrow + g * 4 + j * 32);
    }

    // zero this query's weights row up front (overlaps with K streaming)
    {
        float4 z = make_float4(0.f, 0.f, 0.f, 0.f);
        float4* w4 = reinterpret_cast<float4*>(weights_out + (size_t)n * SS);
        #pragma unroll
        for (int i = tid; i < SS / 4; i += 256) w4[i] = z;
    }

    const float* __restrict__ Ksrc = Kmat + ((size_t)n * SS + warp * 256) * DD;
    float* __restrict__ lwarp = logits + warp * 256;

    #define K1_ISSUE(t)                                                        \
        do {                                                                   \
            float* _dst = kring[warp][(t) & 1];                                \
            const float* _src = Ksrc + (size_t)(t) * 4 * DD;                   \
            _Pragma("unroll")                                                  \
            for (int _i = 0; _i < 4; _i++)                                     \
                cp_async16(&_dst[(lane + 32 * _i) * 4],                        \
                           _src + (lane + 32 * _i) * 4);                       \
            asm volatile("cp.async.commit_group;");                            \
        } while (0)

    K1_ISSUE(0);
    K1_ISSUE(1);

    #pragma unroll 1
    for (int t = 0; t < 64; t++) {
        if (t + 1 < 64) asm volatile("cp.async.wait_group 1;");
        else            asm volatile("cp.async.wait_group 0;");
        __syncwarp();

        const float* kb = &kring[warp][t & 1][row4 * DD];
        float p = 0.f;
        #pragma unroll
        for (int j = 0; j < 4; j++) {
            float4 kv = *reinterpret_cast<const float4*>(kb + g * 4 + j * 32);
            p += qf[j].x * kv.x + qf[j].y * kv.y + qf[j].z * kv.z + qf[j].w * kv.w;
        }
        p += __shfl_xor_sync(0xffffffffu, p, 1);
        p += __shfl_xor_sync(0xffffffffu, p, 2);
        p += __shfl_xor_sync(0xffffffffu, p, 4);
        if (g == 0) lwarp[t * 4 + row4] = p * scale;
        __syncwarp();

        if (t + 2 < 64) K1_ISSUE(t + 2);
    }
    #undef K1_ISSUE

    if (tid == 0) { s_prefix = 0; s_need = TOPK; cA = 0; cE = 0; }
    __syncthreads();

    uint32_t u[8];
    #pragma unroll
    for (int j = 0; j < 8; j++) u[j] = fmono(logits[tid + 256 * j]);

    #pragma unroll 1
    for (int r = 0; r < 4; r++) {
        const int sh = 24 - 8 * r;
        #pragma unroll
        for (int b = 0; b < 4; b++) hist[b][tid] = 0;
        __syncthreads();
        const uint32_t pfx  = s_prefix;
        const int      need = s_need;
        #pragma unroll
        for (int j = 0; j < 8; j++) {
            uint32_t uu = u[j];
            bool ok = (r == 0) || ((uu >> (sh + 8)) == pfx);
            if (ok) atomicAdd(&hist[warp & 3][(uu >> sh) & 255u], 1u);
        }
        __syncthreads();
        uint32_t v = hist[0][tid] + hist[1][tid] + hist[2][tid] + hist[3][tid];
        #pragma unroll
        for (int o = 1; o < 32; o <<= 1) {
            uint32_t t2 = __shfl_down_sync(0xffffffffu, v, o);
            if (lane + o < 32) v += t2;
        }
        if (lane == 0) wsum[warp] = v;
        __syncthreads();
        uint32_t tail = 0;
        #pragma unroll
        for (int w = 0; w < 8; w++) if (w > warp) tail += wsum[w];
        uint32_t ge = v + tail;
        sge[tid] = ge;
        __syncthreads();
        uint32_t ge_next = (tid == 255) ? 0u : sge[tid + 1];
        if (ge >= (uint32_t)need && ge_next < (uint32_t)need) {
            s_prefix = (pfx << 8) | (uint32_t)tid;
            s_need   = need - (int)ge_next;
        }
        __syncthreads();
    }

    const uint32_t ustar  = s_prefix;
    const int      needEq = s_need;

    #pragma unroll
    for (int j = 0; j < 8; j++) {
        uint32_t uu = u[j];
        if (uu > ustar) {
            int p = atomicAdd(&cA, 1);
            if (p < TOPK) s_topi[p] = tid + 256 * j;
        } else if (uu == ustar) {
            int p = atomicAdd(&cE, 1);
            if (p < 64) eqbuf[p] = tid + 256 * j;
        }
    }
    __syncthreads();

    if (warp == 0) {
        const int m = min(cA, TOPK - needEq);
        int E = min(cE, 64);
        int a  = (lane      < E) ? eqbuf[lane]      : 0x7FFFFFFF;
        int b2 = (lane + 32 < E) ? eqbuf[lane + 32] : 0x7FFFFFFF;
        #pragma unroll 1
        for (int t = 0; t < needEq; t++) {
            int mn = min(a, b2);
            #pragma unroll
            for (int o = 16; o > 0; o >>= 1)
                mn = min(mn, __shfl_xor_sync(0xffffffffu, mn, o));
            if (a == mn)       a  = 0x7FFFFFFF;
            else if (b2 == mn) b2 = 0x7FFFFFFF;
            if (lane == 0) s_topi[m + t] = mn;
        }
        __syncwarp();

        float val = logits[s_topi[lane]];
        float mx = val;
        #pragma unroll
        for (int o = 16; o > 0; o >>= 1)
            mx = fmaxf(mx, __shfl_xor_sync(0xffffffffu, mx, o));
        float e = expf(val - mx);
        float denom = warp_sum(e);
        s_w[lane] = e / denom;
    }
    __syncthreads();

    float acc = 0.f;
    if (tid < DD) {
        #pragma unroll
        for (int i = 0; i < TOPK; i++)
            acc += s_w[i] * Vmat[((size_t)n * SS + s_topi[i]) * DD + tid];
    }
    if (tid < DD) g_summary[n * DD + tid] = acc;

    if (tid < TOPK)
        weights_out[(size_t)n * SS + s_topi[tid]] = s_w[tid];
}

// ---------------------------------------------------------------------------
// Readout GEMM chunk (R10 best config): 64x64 tile, 256 threads, 4x4
// micro-tile c-striped, 2 B/FMA. Covers query rows [nBase, nBase+CHUNK).
// grid (18, CHUNK/64): bx<16 -> cls (C=1000), bx 16/17 -> rec (C=128).
// ---------------------------------------------------------------------------
#define GR_STRIDE 132   // floats per row = 33 float4 (odd -> conflict-free)

__global__ __launch_bounds__(256) void readout_gemm(
    const float* __restrict__ Wc, const float* __restrict__ bc, float* __restrict__ outc,
    const float* __restrict__ Wr, const float* __restrict__ br, float* __restrict__ outr,
    int nBase)
{
    extern __shared__ __align__(16) float sm[];
    float* As = sm;                    // 64 x 132
    float* Bs = sm + 64 * GR_STRIDE;   // 64 x 132

    const float* W;  const float* bias;  float* out;  int C;  int cTile;
    if (blockIdx.x < 16) { W = Wc; bias = bc; out = outc; C = CLS; cTile = blockIdx.x * 64; }
    else                 { W = Wr; bias = br; out = outr; C = DD;  cTile = (blockIdx.x - 16) * 64; }

    const int tid   = threadIdx.x;
    const int nTile = nBase + blockIdx.y * 64;

    #pragma unroll
    for (int i = 0; i < 8; i++) {
        int c  = tid + i * 256;      // 0..2047
        int rr = c >> 5;             // 0..63
        int kq = c & 31;
        cp_async16(&As[rr * GR_STRIDE + kq * 4],
                   g_summary + (size_t)(nTile + rr) * DD + kq * 4);
        int cg = cTile + rr;
        if (cg < C)
            cp_async16(&Bs[rr * GR_STRIDE + kq * 4], W + (size_t)cg * DD + kq * 4);
        else
            *reinterpret_cast<float4*>(&Bs[rr * GR_STRIDE + kq * 4]) =
                make_float4(0.f, 0.f, 0.f, 0.f);
    }
    asm volatile("cp.async.commit_group;");
    asm volatile("cp.async.wait_group 0;");
    __syncthreads();

    const int tx = tid & 15;   // c lane within each 16-col stripe
    const int ty = tid >> 4;   // n quad

    const float4* A0 = reinterpret_cast<const float4*>(As + (ty * 4 + 0) * GR_STRIDE);
    const float4* A1 = reinterpret_cast<const float4*>(As + (ty * 4 + 1) * GR_STRIDE);
    const float4* A2 = reinterpret_cast<const float4*>(As + (ty * 4 + 2) * GR_STRIDE);
    const float4* A3 = reinterpret_cast<const float4*>(As + (ty * 4 + 3) * GR_STRIDE);
    const float4* B0 = reinterpret_cast<const float4*>(Bs + ( 0 + tx) * GR_STRIDE);
    const float4* B1 = reinterpret_cast<const float4*>(Bs + (16 + tx) * GR_STRIDE);
    const float4* B2 = reinterpret_cast<const float4*>(Bs + (32 + tx) * GR_STRIDE);
    const float4* B3 = reinterpret_cast<const float4*>(Bs + (48 + tx) * GR_STRIDE);

    float acc[4][4];
    #pragma unroll
    for (int i = 0; i < 4; i++)
        #pragma unroll
        for (int j = 0; j < 4; j++) acc[i][j] = 0.f;

    #pragma unroll 4
    for (int kq = 0; kq < 32; kq++) {
        float4 a[4] = {A0[kq], A1[kq], A2[kq], A3[kq]};
        float4 b[4] = {B0[kq], B1[kq], B2[kq], B3[kq]};
        #pragma unroll
        for (int i = 0; i < 4; i++)
            #pragma unroll
            for (int j = 0; j < 4; j++)
                acc[i][j] += a[i].x * b[j].x + a[i].y * b[j].y +
                             a[i].z * b[j].z + a[i].w * b[j].w;
    }

    #pragma unroll
    for (int i = 0; i < 4; i++) {
        int nn = nTile + ty * 4 + i;
        #pragma unroll
        for (int j = 0; j < 4; j++) {
            int cg = cTile + j * 16 + tx;
            if (cg < C)
                out[(size_t)nn * C + cg] = acc[i][j] + __ldg(&bias[cg]);
        }
    }
}

extern "C" void kernel_launch(void* const* d_in, const int* in_sizes, int n_in,
                              void* d_out, int out_size) {
    const float* q     = (const float*)d_in[0];
    const float* Kmat  = (const float*)d_in[1];
    const float* Vmat  = (const float*)d_in[2];
    const float* W_cls = (const float*)d_in[3];
    const float* b_cls = (const float*)d_in[4];
    const float* W_rec = (const float*)d_in[5];
    const float* b_rec = (const float*)d_in[6];

    float* out = (float*)d_out;
    float* cls = out;
    float* rec = out + (size_t)NQ * CLS;
    float* wts = rec + (size_t)NQ * DD;

    const int gemm_smem = 2 * 64 * GR_STRIDE * 4;   // 67584 B

    static cudaStream_t s2;
    static cudaEvent_t  e1, e2;
    static int init_done = 0;
    if (!init_done) {
        cudaFuncSetAttribute(readout_gemm,
                             cudaFuncAttributeMaxDynamicSharedMemorySize, gemm_smem);
        cudaStreamCreateWithFlags(&s2, cudaStreamNonBlocking);
        cudaEventCreateWithFlags(&e1, cudaEventDisableTiming);
        cudaEventCreateWithFlags(&e2, cudaEventDisableTiming);
        init_done = 1;
    }

    // A1: queries [0, 256)
    attn_topk_kernel<<<CHUNK, 256>>>(q, Kmat, Vmat, wts, 0);
    cudaEventRecord(e1, 0);

    // G1 on side stream: rows [0, 256) — overlaps A2's streaming
    cudaStreamWaitEvent(s2, e1, 0);
    readout_gemm<<<dim3(18, CHUNK / 64), 256, gemm_smem, s2>>>(
        W_cls, b_cls, cls, W_rec, b_rec, rec, 0);
    cudaEventRecord(e2, s2);

    // A2: queries [256, 512) on the main stream (no dependency on G1)
    attn_topk_kernel<<<CHUNK, 256>>>(q, Kmat, Vmat, wts, CHUNK);

    // G2: rows [256, 512) — the only visible GEMM tail
    readout_gemm<<<dim3(18, CHUNK / 64), 256, gemm_smem>>>(
        W_cls, b_cls, cls, W_rec, b_rec, rec, CHUNK);

    // join side stream back into the capture stream
    cudaStreamWaitEvent(0, e2, 0);
}

// round 17
// speedup vs baseline: 1.0790x; 1.0790x over previous
#include <cuda_runtime.h>
#include <cstdint>

#define NQ   512
#define SS   2048
#define DD   128
#define TOPK 32
#define CLS  1000

__device__ float g_summary[NQ * DD];

__device__ __forceinline__ float warp_sum(float v) {
    #pragma unroll
    for (int o = 16; o > 0; o >>= 1) v += __shfl_xor_sync(0xffffffffu, v, o);
    return v;
}

__device__ __forceinline__ void cp_async16(void* smem, const void* gmem) {
    uint32_t s = (uint32_t)__cvta_generic_to_shared(smem);
    asm volatile("cp.async.cg.shared.global [%0], [%1], 16;" :: "r"(s), "l"(gmem));
}

__device__ __forceinline__ uint32_t fmono(float x) {
    uint32_t b = __float_as_uint(x);
    return (b & 0x80000000u) ? ~b : (b | 0x80000000u);
}

__device__ __forceinline__ uint32_t to_tf32(float v) {
    uint32_t r;
    asm("cvt.rna.tf32.f32 %0, %1;" : "=r"(r) : "f"(v));
    return r;
}

__device__ __forceinline__ void mma_tf32(float4& d,
    uint32_t a0, uint32_t a1, uint32_t a2, uint32_t a3,
    uint32_t b0, uint32_t b1)
{
    asm volatile(
        "mma.sync.aligned.m16n8k8.row.col.f32.tf32.tf32.f32 "
        "{%0,%1,%2,%3}, {%4,%5,%6,%7}, {%8,%9}, {%0,%1,%2,%3};"
        : "+f"(d.x), "+f"(d.y), "+f"(d.z), "+f"(d.w)
        : "r"(a0), "r"(a1), "r"(a2), "r"(a3), "r"(b0), "r"(b1));
}

// ---------------------------------------------------------------------------
// Fused attention (identical to R11 best): cp.async K streaming, radix-select
// top-32, softmax, V gather; weights row zeroed up front, scatter at end.
// ---------------------------------------------------------------------------
__global__ __launch_bounds__(256) void attn_topk_kernel(
    const float* __restrict__ q,
    const float* __restrict__ Kmat,
    const float* __restrict__ Vmat,
    float* __restrict__ weights_out)
{
    const int n    = blockIdx.x;
    const int tid  = threadIdx.x;
    const int warp = tid >> 5;
    const int lane = tid & 31;
    const int row4 = lane >> 3;
    const int g    = lane & 7;

    __shared__ __align__(16) float kring[8][2][4 * DD];  // 32 KB
    __shared__ float logits[SS];                         // 8 KB
    __shared__ uint32_t hist[4][256];                    // 4 KB
    __shared__ uint32_t sge[256];                        // 1 KB
    __shared__ uint32_t wsum[8];
    __shared__ int   s_topi[TOPK];
    __shared__ float s_w[TOPK];
    __shared__ int   eqbuf[64];
    __shared__ uint32_t s_prefix;
    __shared__ int   s_need, cA, cE;

    const float scale = 0.08838834764831845f; // 1/sqrt(128)

    float4 qf[4];
    {
        const float* qrow = q + (size_t)n * DD;
        #pragma unroll
        for (int j = 0; j < 4; j++)
            qf[j] = *reinterpret_cast<const float4*>(qrow + g * 4 + j * 32);
    }

    // zero this query's weights row up front (overlaps with K streaming)
    {
        float4 z = make_float4(0.f, 0.f, 0.f, 0.f);
        float4* w4 = reinterpret_cast<float4*>(weights_out + (size_t)n * SS);
        #pragma unroll
        for (int i = tid; i < SS / 4; i += 256) w4[i] = z;
    }

    const float* __restrict__ Ksrc = Kmat + ((size_t)n * SS + warp * 256) * DD;
    float* __restrict__ lwarp = logits + warp * 256;

    #define K1_ISSUE(t)                                                        \
        do {                                                                   \
            float* _dst = kring[warp][(t) & 1];                                \
            const float* _src = Ksrc + (size_t)(t) * 4 * DD;                   \
            _Pragma("unroll")                                                  \
            for (int _i = 0; _i < 4; _i++)                                     \
                cp_async16(&_dst[(lane + 32 * _i) * 4],                        \
                           _src + (lane + 32 * _i) * 4);                       \
            asm volatile("cp.async.commit_group;");                            \
        } while (0)

    K1_ISSUE(0);
    K1_ISSUE(1);

    #pragma unroll 1
    for (int t = 0; t < 64; t++) {
        if (t + 1 < 64) asm volatile("cp.async.wait_group 1;");
        else            asm volatile("cp.async.wait_group 0;");
        __syncwarp();

        const float* kb = &kring[warp][t & 1][row4 * DD];
        float p = 0.f;
        #pragma unroll
        for (int j = 0; j < 4; j++) {
            float4 kv = *reinterpret_cast<const float4*>(kb + g * 4 + j * 32);
            p += qf[j].x * kv.x + qf[j].y * kv.y + qf[j].z * kv.z + qf[j].w * kv.w;
        }
        p += __shfl_xor_sync(0xffffffffu, p, 1);
        p += __shfl_xor_sync(0xffffffffu, p, 2);
        p += __shfl_xor_sync(0xffffffffu, p, 4);
        if (g == 0) lwarp[t * 4 + row4] = p * scale;
        __syncwarp();

        if (t + 2 < 64) K1_ISSUE(t + 2);
    }
    #undef K1_ISSUE

    if (tid == 0) { s_prefix = 0; s_need = TOPK; cA = 0; cE = 0; }
    __syncthreads();

    uint32_t u[8];
    #pragma unroll
    for (int j = 0; j < 8; j++) u[j] = fmono(logits[tid + 256 * j]);

    #pragma unroll 1
    for (int r = 0; r < 4; r++) {
        const int sh = 24 - 8 * r;
        #pragma unroll
        for (int b = 0; b < 4; b++) hist[b][tid] = 0;
        __syncthreads();
        const uint32_t pfx  = s_prefix;
        const int      need = s_need;
        #pragma unroll
        for (int j = 0; j < 8; j++) {
            uint32_t uu = u[j];
            bool ok = (r == 0) || ((uu >> (sh + 8)) == pfx);
            if (ok) atomicAdd(&hist[warp & 3][(uu >> sh) & 255u], 1u);
        }
        __syncthreads();
        uint32_t v = hist[0][tid] + hist[1][tid] + hist[2][tid] + hist[3][tid];
        #pragma unroll
        for (int o = 1; o < 32; o <<= 1) {
            uint32_t t2 = __shfl_down_sync(0xffffffffu, v, o);
            if (lane + o < 32) v += t2;
        }
        if (lane == 0) wsum[warp] = v;
        __syncthreads();
        uint32_t tail = 0;
        #pragma unroll
        for (int w = 0; w < 8; w++) if (w > warp) tail += wsum[w];
        uint32_t ge = v + tail;
        sge[tid] = ge;
        __syncthreads();
        uint32_t ge_next = (tid == 255) ? 0u : sge[tid + 1];
        if (ge >= (uint32_t)need && ge_next < (uint32_t)need) {
            s_prefix = (pfx << 8) | (uint32_t)tid;
            s_need   = need - (int)ge_next;
        }
        __syncthreads();
    }

    const uint32_t ustar  = s_prefix;
    const int      needEq = s_need;

    #pragma unroll
    for (int j = 0; j < 8; j++) {
        uint32_t uu = u[j];
        if (uu > ustar) {
            int p = atomicAdd(&cA, 1);
            if (p < TOPK) s_topi[p] = tid + 256 * j;
        } else if (uu == ustar) {
            int p = atomicAdd(&cE, 1);
            if (p < 64) eqbuf[p] = tid + 256 * j;
        }
    }
    __syncthreads();

    if (warp == 0) {
        const int m = min(cA, TOPK - needEq);
        int E = min(cE, 64);
        int a  = (lane      < E) ? eqbuf[lane]      : 0x7FFFFFFF;
        int b2 = (lane + 32 < E) ? eqbuf[lane + 32] : 0x7FFFFFFF;
        #pragma unroll 1
        for (int t = 0; t < needEq; t++) {
            int mn = min(a, b2);
            #pragma unroll
            for (int o = 16; o > 0; o >>= 1)
                mn = min(mn, __shfl_xor_sync(0xffffffffu, mn, o));
            if (a == mn)       a  = 0x7FFFFFFF;
            else if (b2 == mn) b2 = 0x7FFFFFFF;
            if (lane == 0) s_topi[m + t] = mn;
        }
        __syncwarp();

        float val = logits[s_topi[lane]];
        float mx = val;
        #pragma unroll
        for (int o = 16; o > 0; o >>= 1)
            mx = fmaxf(mx, __shfl_xor_sync(0xffffffffu, mx, o));
        float e = expf(val - mx);
        float denom = warp_sum(e);
        s_w[lane] = e / denom;
    }
    __syncthreads();

    float acc = 0.f;
    if (tid < DD) {
        #pragma unroll
        for (int i = 0; i < TOPK; i++)
            acc += s_w[i] * Vmat[((size_t)n * SS + s_topi[i]) * DD + tid];
    }
    if (tid < DD) g_summary[n * DD + tid] = acc;
    __syncthreads();

    // publish g_summary -> dependent GEMM may proceed
    if (tid == 0) {
        __threadfence();
        asm volatile("griddepcontrol.launch_dependents;");
    }

    if (tid < TOPK)
        weights_out[(size_t)n * SS + s_topi[tid]] = s_w[tid];
}

// ---------------------------------------------------------------------------
// Readout GEMMs via tf32 tensor-core mma.sync (m16n8k8): breaks the ~4.9us
// FFMA-issue floor that pinned every FFMA variant at ~10-12us.
// 64x64 tile, 256 threads = 8 warps in 4(row)x2(col) arrangement; each warp
// computes 16 rows x 32 cols = 4 mma col-tiles x 16 k-steps.
// smem staged once via cp.async (B before PDL wait, A after).
// grid (18, 8): bx<16 -> cls (C=1000), bx 16/17 -> rec (C=128).
// ---------------------------------------------------------------------------
#define GR_STRIDE 132   // floats per row; 132 mod 32 = 4 -> conflict-free frags

__global__ __launch_bounds__(256) void readout_gemm(
    const float* __restrict__ Wc, const float* __restrict__ bc, float* __restrict__ outc,
    const float* __restrict__ Wr, const float* __restrict__ br, float* __restrict__ outr)
{
    extern __shared__ __align__(16) float sm[];
    float* As = sm;                    // 64 x 132  (summary rows)
    float* Bs = sm + 64 * GR_STRIDE;   // 64 x 132  (W rows)

    const float* W;  const float* bias;  float* out;  int C;  int cTile;
    if (blockIdx.x < 16) { W = Wc; bias = bc; out = outc; C = CLS; cTile = blockIdx.x * 64; }
    else                 { W = Wr; bias = br; out = outr; C = DD;  cTile = (blockIdx.x - 16) * 64; }

    const int tid   = threadIdx.x;
    const int nTile = blockIdx.y * 64;

    // ---- stage B (independent of attention output) ----
    #pragma unroll
    for (int i = 0; i < 8; i++) {
        int c  = tid + i * 256;      // 0..2047
        int rr = c >> 5;             // 0..63
        int kq = c & 31;
        int cg = cTile + rr;
        if (cg < C)
            cp_async16(&Bs[rr * GR_STRIDE + kq * 4], W + (size_t)cg * DD + kq * 4);
        else
            *reinterpret_cast<float4*>(&Bs[rr * GR_STRIDE + kq * 4]) =
                make_float4(0.f, 0.f, 0.f, 0.f);
    }
    asm volatile("cp.async.commit_group;");

    // ---- wait for attention grid to publish g_summary ----
    asm volatile("griddepcontrol.wait;");

    // ---- stage A ----
    #pragma unroll
    for (int i = 0; i < 8; i++) {
        int c  = tid + i * 256;
        int rr = c >> 5;
        int kq = c & 31;
        cp_async16(&As[rr * GR_STRIDE + kq * 4],
                   g_summary + (size_t)(nTile + rr) * DD + kq * 4);
    }
    asm volatile("cp.async.commit_group;");
    asm volatile("cp.async.wait_group 0;");
    __syncthreads();

    const int warp = tid >> 5;
    const int lane = tid & 31;
    const int gid  = lane >> 2;      // groupID 0..7
    const int tig  = lane & 3;       // threadID_in_group 0..3
    const int wr   = warp & 3;       // warp row: n rows [wr*16, +16)
    const int wq   = warp >> 2;      // warp col: c cols [wq*32, +32)

    const float* Arow0 = As + (wr * 16 + gid)     * GR_STRIDE;
    const float* Arow1 = As + (wr * 16 + gid + 8) * GR_STRIDE;

    float4 acc[4];
    #pragma unroll
    for (int j = 0; j < 4; j++) acc[j] = make_float4(0.f, 0.f, 0.f, 0.f);

    #pragma unroll 4
    for (int kt = 0; kt < 16; kt++) {
        const int k0 = kt * 8;
        uint32_t a0 = to_tf32(Arow0[k0 + tig]);
        uint32_t a1 = to_tf32(Arow1[k0 + tig]);
        uint32_t a2 = to_tf32(Arow0[k0 + tig + 4]);
        uint32_t a3 = to_tf32(Arow1[k0 + tig + 4]);
        #pragma unroll
        for (int j = 0; j < 4; j++) {
            const float* Brow = Bs + (wq * 32 + j * 8 + gid) * GR_STRIDE;
            uint32_t b0 = to_tf32(Brow[k0 + tig]);
            uint32_t b1 = to_tf32(Brow[k0 + tig + 4]);
            mma_tf32(acc[j], a0, a1, a2, a3, b0, b1);
        }
    }

    // D fragment: c0=(row0, 2*tig), c1=(row0, 2*tig+1), c2/c3 = row0+8
    const int row0 = nTile + wr * 16 + gid;
    #pragma unroll
    for (int j = 0; j < 4; j++) {
        int col = cTile + wq * 32 + j * 8 + 2 * tig;
        if (col < C) {
            float bb = __ldg(&bias[col]);
            out[(size_t)(row0    ) * C + col] = acc[j].x + bb;
            out[(size_t)(row0 + 8) * C + col] = acc[j].z + bb;
        }
        if (col + 1 < C) {
            float bb = __ldg(&bias[col + 1]);
            out[(size_t)(row0    ) * C + col + 1] = acc[j].y + bb;
            out[(size_t)(row0 + 8) * C + col + 1] = acc[j].w + bb;
        }
    }
}

extern "C" void kernel_launch(void* const* d_in, const int* in_sizes, int n_in,
                              void* d_out, int out_size) {
    const float* q     = (const float*)d_in[0];
    const float* Kmat  = (const float*)d_in[1];
    const float* Vmat  = (const float*)d_in[2];
    const float* W_cls = (const float*)d_in[3];
    const float* b_cls = (const float*)d_in[4];
    const float* W_rec = (const float*)d_in[5];
    const float* b_rec = (const float*)d_in[6];

    float* out = (float*)d_out;
    float* cls = out;
    float* rec = out + (size_t)NQ * CLS;
    float* wts = rec + (size_t)NQ * DD;

    const int gemm_smem = 2 * 64 * GR_STRIDE * 4;   // 67584 B
    static int attr_set = 0;
    if (!attr_set) {
        cudaFuncSetAttribute(readout_gemm,
                             cudaFuncAttributeMaxDynamicSharedMemorySize, gemm_smem);
        attr_set = 1;
    }

    attn_topk_kernel<<<NQ, 256>>>(q, Kmat, Vmat, wts);

    cudaLaunchConfig_t cfg = {};
    cfg.gridDim  = dim3(18, 8, 1);
    cfg.blockDim = dim3(256, 1, 1);
    cfg.dynamicSmemBytes = gemm_smem;
    cfg.stream = 0;
    cudaLaunchAttribute at[1];
    at[0].id = cudaLaunchAttributeProgrammaticStreamSerialization;
    at[0].val.programmaticStreamSerializationAllowed = 1;
    cfg.attrs = at;
    cfg.numAttrs = 1;
    cudaLaunchKernelEx(&cfg, readout_gemm, W_cls, b_cls, cls, W_rec, b_rec, rec);
}